// round 15
// baseline (speedup 1.0000x reference)
#include <cuda_runtime.h>
#include <math.h>

#define BB 2
#define SS 2048
#define DD 1024
#define HH 16
#define HD 64
#define D3 3072
#define NEGM (-1e9f)
#define KC 512          // qkv/proj panel depth (matched to reference, R14 WIN)
#define KCPV_TILES 8    // PV panel = 8 tiles * 64 = 512 keys

__device__ float g_qkv[(size_t)BB * SS * D3];
__device__ float g_attn[(size_t)BB * SS * DD];
__device__ float g_S[(size_t)BB * HH * SS * SS];   // scores -> probs scratch
__device__ unsigned g_max[3];

// ---- XLA GenerateVF32Exp (Cephes; unfused range reduction; exact 0 underflow)
__device__ __forceinline__ float xla_expf(float x) {
    x = fminf(fmaxf(x, -88.3762626647949f), 88.3762626647950f);
    float fx = floorf(__fmaf_rn(x, 1.44269504088896341f, 0.5f));
    float tmp = __fmul_rn(fx, 0.693359375f);
    float z = __fmul_rn(fx, -2.12194440e-4f);
    x = __fadd_rn(x, -tmp);
    x = __fadd_rn(x, -z);
    z = __fmul_rn(x, x);
    float y = 1.9875691500e-4f;
    y = __fmaf_rn(y, x, 1.3981999507e-3f);
    y = __fmaf_rn(y, x, 8.3334519073e-3f);
    y = __fmaf_rn(y, x, 4.1665795894e-2f);
    y = __fmaf_rn(y, x, 1.6666665459e-1f);
    y = __fmaf_rn(y, x, 5.0000001201e-1f);
    y = __fmaf_rn(y, z, x);
    y = __fadd_rn(y, 1.0f);
    int n = (int)fx;
    float p2n = __int_as_float((n + 127) << 23);
    return __fmul_rn(y, p2n);
}

__global__ void k_init() {
    if (threadIdx.x < 3) g_max[threadIdx.x] = 0u;
}

__global__ void k_absmax_kv() {
    const long long n = (long long)BB * SS * DD;
    float mk = 0.f, mv = 0.f;
    for (long long i = (long long)blockIdx.x * blockDim.x + threadIdx.x; i < n;
         i += (long long)gridDim.x * blockDim.x) {
        long long bs = i >> 10;
        int c = (int)(i & 1023);
        const float* row = g_qkv + bs * D3;
        mk = fmaxf(mk, fabsf(row[DD + c]));
        mv = fmaxf(mv, fabsf(row[2 * DD + c]));
    }
    #pragma unroll
    for (int o = 16; o; o >>= 1) {
        mk = fmaxf(mk, __shfl_xor_sync(0xffffffffu, mk, o));
        mv = fmaxf(mv, __shfl_xor_sync(0xffffffffu, mv, o));
    }
    if ((threadIdx.x & 31) == 0) {
        atomicMax(&g_max[0], __float_as_uint(mk));
        atomicMax(&g_max[1], __float_as_uint(mv));
    }
}

__global__ void k_absmax_o() {
    const long long n = (long long)BB * SS * DD;
    float m = 0.f;
    for (long long i = (long long)blockIdx.x * blockDim.x + threadIdx.x; i < n;
         i += (long long)gridDim.x * blockDim.x)
        m = fmaxf(m, fabsf(g_attn[i]));
    #pragma unroll
    for (int o = 16; o; o >>= 1) m = fmaxf(m, __shfl_xor_sync(0xffffffffu, m, o));
    if ((threadIdx.x & 31) == 0) atomicMax(&g_max[2], __float_as_uint(m));
}

__global__ void k_quant_kv(float* __restrict__ present) {
    const long long total = (long long)BB * SS * DD;
    const float sk = __fdiv_rn(__uint_as_float(g_max[0]), 127.0f);
    const float sv = __fdiv_rn(__uint_as_float(g_max[1]), 127.0f);
    for (long long t = (long long)blockIdx.x * blockDim.x + threadIdx.x; t < 2 * total;
         t += (long long)gridDim.x * blockDim.x) {
        int half = (int)(t / total);
        long long i = t - (long long)half * total;
        long long bs = i >> 10;
        int c = (int)(i & 1023);
        float sc = half ? sv : sk;
        long long adr = bs * D3 + (long long)DD * (1 + half) + c;
        float x = g_qkv[adr];
        float q = rintf(__fdiv_rn(x, sc));
        q = __fmul_rn(fminf(fmaxf(q, -128.f), 127.f), sc);
        g_qkv[adr] = q;
        if (present) {
            int h = c >> 6, d = c & 63;
            int s = (int)(bs & (SS - 1));
            int b = (int)(bs >> 11);
            present[(long long)half * total +
                    (((long long)(b * HH + h) * SS + s) << 6) + d] = q;
        }
    }
}

// ---- SGEMM: serial ascending chains inside kc=512 panels, C += per panel ---
template <int MODE>
__global__ void k_gemm(const float* __restrict__ Ain, const float* __restrict__ W,
                       const float* __restrict__ bias, float* __restrict__ Cout,
                       int M, int N, int K) {
    __shared__ float As[16][64];
    __shared__ float Ws[16][64];
    const int tid = threadIdx.x;
    const int ty = tid >> 4, tx = tid & 15;
    const int m0 = blockIdx.y * 64, n0 = blockIdx.x * 64;
    const int lc = tid & 15;
    const int lr = (tid >> 4) * 4;

    const float* A = (MODE == 0) ? Ain : g_attn;
    float* C = (MODE == 0) ? g_qkv : Cout;
    float qs = 1.0f;
    if (MODE == 1) qs = __fdiv_rn(__uint_as_float(g_max[2]), 127.0f);

    float acc[4][4] = {};
    float accT[4][4] = {};
    for (int k0 = 0; k0 < K; k0 += 16) {
        #pragma unroll
        for (int ii = 0; ii < 4; ii++) {
            float a = A[(long long)(m0 + lr + ii) * K + k0 + lc];
            if (MODE == 1) {
                float q = rintf(__fdiv_rn(a, qs));
                a = __fmul_rn(fminf(fmaxf(q, -128.f), 127.f), qs);
            }
            As[lc][lr + ii] = a;
            Ws[lc][lr + ii] = W[(long long)(n0 + lr + ii) * K + k0 + lc];
        }
        __syncthreads();
        #pragma unroll
        for (int kk = 0; kk < 16; kk++) {
            float4 af = *(const float4*)&As[kk][ty * 4];
            float4 wf = *(const float4*)&Ws[kk][tx * 4];
            float aa[4] = {af.x, af.y, af.z, af.w};
            float ww[4] = {wf.x, wf.y, wf.z, wf.w};
            #pragma unroll
            for (int i = 0; i < 4; i++)
                #pragma unroll
                for (int j = 0; j < 4; j++)
                    acc[i][j] = __fmaf_rn(aa[i], ww[j], acc[i][j]);
        }
        if (((k0 + 16) % KC == 0) || (k0 + 16 == K)) {
            #pragma unroll
            for (int i = 0; i < 4; i++)
                #pragma unroll
                for (int j = 0; j < 4; j++) {
                    accT[i][j] = __fadd_rn(accT[i][j], acc[i][j]);
                    acc[i][j] = 0.f;
                }
        }
        __syncthreads();
    }
    #pragma unroll
    for (int i = 0; i < 4; i++)
        #pragma unroll
        for (int j = 0; j < 4; j++)
            C[(long long)(m0 + ty * 4 + i) * N + n0 + tx * 4 + j] =
                __fadd_rn(accT[i][j], bias[n0 + tx * 4 + j]);
}

// ---- score tile: bitwise-identical to R14 ----------------------------------
__device__ __forceinline__ void score_tile(const float* __restrict__ Qs,
                                           const float* __restrict__ Ks,
                                           int ty, int tx, int qt, int kb,
                                           float s[4][4]) {
    float a0[4][4] = {};
    #pragma unroll 8
    for (int d = 0; d < 64; d++) {
        float4 qf = *(const float4*)&Qs[d * 64 + ty * 4];
        float4 kf = *(const float4*)&Ks[d * 64 + tx * 4];
        float qa[4] = {qf.x, qf.y, qf.z, qf.w};
        float ka[4] = {kf.x, kf.y, kf.z, kf.w};
        #pragma unroll
        for (int i = 0; i < 4; i++)
            #pragma unroll
            for (int j = 0; j < 4; j++)
                a0[i][j] = __fmaf_rn(qa[i], ka[j], a0[i][j]);
    }
    #pragma unroll
    for (int i = 0; i < 4; i++)
        #pragma unroll
        for (int j = 0; j < 4; j++) {
            float v = __fmul_rn(a0[i][j], 0.125f);
            if (kb == qt && (tx * 4 + j) > (ty * 4 + i)) v = __fadd_rn(v, NEGM);
            s[i][j] = v;
        }
}

// ---- stage 1: compute S once, store to gmem (causal tiles only) ------------
__global__ void k_score() {
    __shared__ float Qs[4096];
    __shared__ float Ks[4096];
    const int tid = threadIdx.x;
    const int ty = tid >> 4, tx = tid & 15;
    const int qt = blockIdx.x;
    const int bh = blockIdx.y;
    const int b = bh >> 4, h = bh & 15;
    const int q0 = qt * 64;

    const float* qbase = g_qkv + ((long long)(b * SS + q0)) * D3 + h * HD;
    for (int idx = tid; idx < 4096; idx += 256) {
        int r = idx >> 6, d = idx & 63;
        Qs[d * 64 + r] = qbase[(long long)r * D3 + d];
    }
    const float* kbase = g_qkv + (long long)b * SS * D3 + DD + h * HD;
    float* Srow = g_S + (long long)bh * SS * SS;

    for (int kb = 0; kb <= qt; kb++) {
        __syncthreads();
        const int c0 = kb * 64;
        for (int idx = tid; idx < 4096; idx += 256) {
            int c = idx >> 6, d = idx & 63;
            Ks[d * 64 + c] = kbase[(long long)(c0 + c) * D3 + d];
        }
        __syncthreads();
        float s[4][4];
        score_tile(Qs, Ks, ty, tx, qt, kb, s);
        #pragma unroll
        for (int i = 0; i < 4; i++) {
            float4 v = make_float4(s[i][0], s[i][1], s[i][2], s[i][3]);
            *(float4*)&Srow[(long long)(q0 + ty * 4 + i) * SS + c0 + tx * 4] = v;
        }
    }
}

// ---- stage 2: per-row serial max -> exp+l (ascending) -> p=e/l in place ----
__global__ void k_softrow() {
    int row = blockIdx.x * blockDim.x + threadIdx.x;   // 0 .. B*H*S-1
    if (row >= BB * HH * SS) return;
    int q = row & (SS - 1);
    float* S = g_S + (long long)row * SS;
    const int kmax = ((q >> 6) + 1) << 6;   // tiles 0..qt inclusive (as R14)

    float m = -INFINITY;
    for (int c = 0; c < kmax; c++) m = fmaxf(m, S[c]);   // max: order-exact
    float l = 0.f;
    for (int c = 0; c < kmax; c++) {                     // serial ascending
        float e = xla_expf(__fadd_rn(S[c], -m));
        S[c] = e;
        l = __fadd_rn(l, e);
    }
    for (int c = 0; c < kmax; c++) S[c] = __fdiv_rn(S[c], l);
}

// ---- stage 3: O = P*V, 512-key panels, serial chains (bitwise = R14) -------
__global__ void k_pv() {
    __shared__ float Vs[4096];
    __shared__ float Ps[4096];
    const int tid = threadIdx.x;
    const int ty = tid >> 4, tx = tid & 15;
    const int qt = blockIdx.x;
    const int bh = blockIdx.y;
    const int b = bh >> 4, h = bh & 15;
    const int q0 = qt * 64;

    const float* vbase = g_qkv + (long long)b * SS * D3 + 2 * DD + h * HD;
    const float* Prow = g_S + (long long)bh * SS * SS;

    float o[4][4] = {};
    float op[4][4] = {};
    for (int kb = 0; kb <= qt; kb++) {
        __syncthreads();
        const int c0 = kb * 64;
        for (int idx = tid; idx < 4096; idx += 256) {
            int r = idx >> 6, c = idx & 63;
            Ps[c * 64 + r] = Prow[(long long)(q0 + r) * SS + c0 + c];
            Vs[r * 64 + c] = vbase[(long long)(c0 + r) * D3 + c];
        }
        __syncthreads();
        #pragma unroll 8
        for (int c = 0; c < 64; c++) {
            float4 pf = *(const float4*)&Ps[c * 64 + ty * 4];
            float4 vf = *(const float4*)&Vs[c * 64 + tx * 4];
            float pa[4] = {pf.x, pf.y, pf.z, pf.w};
            float va[4] = {vf.x, vf.y, vf.z, vf.w};
            #pragma unroll
            for (int i = 0; i < 4; i++)
                #pragma unroll
                for (int j = 0; j < 4; j++)
                    op[i][j] = __fmaf_rn(pa[i], va[j], op[i][j]);
        }
        if (((kb + 1) % KCPV_TILES == 0) || (kb == qt)) {
            #pragma unroll
            for (int i = 0; i < 4; i++)
                #pragma unroll
                for (int j = 0; j < 4; j++) {
                    o[i][j] = __fadd_rn(o[i][j], op[i][j]);
                    op[i][j] = 0.f;
                }
        }
    }

    float* obase = g_attn + ((long long)(b * SS + q0)) * DD + h * HD;
    #pragma unroll
    for (int i = 0; i < 4; i++)
        #pragma unroll
        for (int j = 0; j < 4; j++)
            obase[(long long)(ty * 4 + i) * DD + tx * 4 + j] = o[i][j];
}

// ---- launch -----------------------------------------------------------------
extern "C" void kernel_launch(void* const* d_in, const int* in_sizes, int n_in,
                              void* d_out, int out_size) {
    const float* hidden = (const float*)d_in[0];
    const float* W_attn = (const float*)d_in[2];
    const float* b_attn = (const float*)d_in[3];
    const float* W_proj = (const float*)d_in[4];
    const float* b_proj = (const float*)d_in[5];
    float* out = (float*)d_out;

    const long long total = (long long)BB * SS * DD;
    float* present = (out_size >= (int)(3 * total)) ? (out + total) : nullptr;

    k_gemm<0><<<dim3(D3 / 64, (BB * SS) / 64), 256>>>(hidden, W_attn, b_attn, nullptr,
                                                      BB * SS, D3, DD);
    k_init<<<1, 32>>>();
    k_absmax_kv<<<1024, 256>>>();
    k_quant_kv<<<2048, 256>>>(present);
    k_score<<<dim3(SS / 64, BB * HH), 256>>>();
    k_softrow<<<(BB * HH * SS + 255) / 256, 256>>>();
    k_pv<<<dim3(SS / 64, BB * HH), 256>>>();
    k_absmax_o<<<1024, 256>>>();
    k_gemm<1><<<dim3(DD / 64, (BB * SS) / 64), 256>>>(nullptr, W_proj, b_proj, out,
                                                      BB * SS, DD, DD);
}

// round 16
// speedup vs baseline: 1.8197x; 1.8197x over previous
#include <cuda_runtime.h>
#include <math.h>

#define BB 2
#define SS 2048
#define DD 1024
#define HH 16
#define HD 64
#define D3 3072
#define NEGM (-1e9f)
#define KC 512          // qkv/proj panel depth (matched to reference, R14 WIN)
#define KCPV_TILES 8    // PV panel = 8 tiles * 64 = 512 keys

__device__ float g_qkv[(size_t)BB * SS * D3];
__device__ float g_attn[(size_t)BB * SS * DD];
__device__ float g_S[(size_t)BB * HH * SS * SS];     // scores -> e scratch
__device__ float g_pmax[(size_t)BB * HH * SS * 32];  // per-(row,tile) max
__device__ unsigned g_max[3];

// ---- XLA GenerateVF32Exp (Cephes; unfused range reduction; exact 0 underflow)
__device__ __forceinline__ float xla_expf(float x) {
    x = fminf(fmaxf(x, -88.3762626647949f), 88.3762626647950f);
    float fx = floorf(__fmaf_rn(x, 1.44269504088896341f, 0.5f));
    float tmp = __fmul_rn(fx, 0.693359375f);
    float z = __fmul_rn(fx, -2.12194440e-4f);
    x = __fadd_rn(x, -tmp);
    x = __fadd_rn(x, -z);
    z = __fmul_rn(x, x);
    float y = 1.9875691500e-4f;
    y = __fmaf_rn(y, x, 1.3981999507e-3f);
    y = __fmaf_rn(y, x, 8.3334519073e-3f);
    y = __fmaf_rn(y, x, 4.1665795894e-2f);
    y = __fmaf_rn(y, x, 1.6666665459e-1f);
    y = __fmaf_rn(y, x, 5.0000001201e-1f);
    y = __fmaf_rn(y, z, x);
    y = __fadd_rn(y, 1.0f);
    int n = (int)fx;
    float p2n = __int_as_float((n + 127) << 23);
    return __fmul_rn(y, p2n);
}

__global__ void k_init() {
    if (threadIdx.x < 3) g_max[threadIdx.x] = 0u;
}

__global__ void k_absmax_kv() {
    const long long n = (long long)BB * SS * DD;
    float mk = 0.f, mv = 0.f;
    for (long long i = (long long)blockIdx.x * blockDim.x + threadIdx.x; i < n;
         i += (long long)gridDim.x * blockDim.x) {
        long long bs = i >> 10;
        int c = (int)(i & 1023);
        const float* row = g_qkv + bs * D3;
        mk = fmaxf(mk, fabsf(row[DD + c]));
        mv = fmaxf(mv, fabsf(row[2 * DD + c]));
    }
    #pragma unroll
    for (int o = 16; o; o >>= 1) {
        mk = fmaxf(mk, __shfl_xor_sync(0xffffffffu, mk, o));
        mv = fmaxf(mv, __shfl_xor_sync(0xffffffffu, mv, o));
    }
    if ((threadIdx.x & 31) == 0) {
        atomicMax(&g_max[0], __float_as_uint(mk));
        atomicMax(&g_max[1], __float_as_uint(mv));
    }
}

__global__ void k_absmax_o() {
    const long long n = (long long)BB * SS * DD;
    float m = 0.f;
    for (long long i = (long long)blockIdx.x * blockDim.x + threadIdx.x; i < n;
         i += (long long)gridDim.x * blockDim.x)
        m = fmaxf(m, fabsf(g_attn[i]));
    #pragma unroll
    for (int o = 16; o; o >>= 1) m = fmaxf(m, __shfl_xor_sync(0xffffffffu, m, o));
    if ((threadIdx.x & 31) == 0) atomicMax(&g_max[2], __float_as_uint(m));
}

__global__ void k_quant_kv(float* __restrict__ present) {
    const long long total = (long long)BB * SS * DD;
    const float sk = __fdiv_rn(__uint_as_float(g_max[0]), 127.0f);
    const float sv = __fdiv_rn(__uint_as_float(g_max[1]), 127.0f);
    for (long long t = (long long)blockIdx.x * blockDim.x + threadIdx.x; t < 2 * total;
         t += (long long)gridDim.x * blockDim.x) {
        int half = (int)(t / total);
        long long i = t - (long long)half * total;
        long long bs = i >> 10;
        int c = (int)(i & 1023);
        float sc = half ? sv : sk;
        long long adr = bs * D3 + (long long)DD * (1 + half) + c;
        float x = g_qkv[adr];
        float q = rintf(__fdiv_rn(x, sc));
        q = __fmul_rn(fminf(fmaxf(q, -128.f), 127.f), sc);
        g_qkv[adr] = q;
        if (present) {
            int h = c >> 6, d = c & 63;
            int s = (int)(bs & (SS - 1));
            int b = (int)(bs >> 11);
            present[(long long)half * total +
                    (((long long)(b * HH + h) * SS + s) << 6) + d] = q;
        }
    }
}

// ---- SGEMM: serial ascending chains inside kc=512 panels, C += per panel ---
template <int MODE>
__global__ void k_gemm(const float* __restrict__ Ain, const float* __restrict__ W,
                       const float* __restrict__ bias, float* __restrict__ Cout,
                       int M, int N, int K) {
    __shared__ float As[16][64];
    __shared__ float Ws[16][64];
    const int tid = threadIdx.x;
    const int ty = tid >> 4, tx = tid & 15;
    const int m0 = blockIdx.y * 64, n0 = blockIdx.x * 64;
    const int lc = tid & 15;
    const int lr = (tid >> 4) * 4;

    const float* A = (MODE == 0) ? Ain : g_attn;
    float* C = (MODE == 0) ? g_qkv : Cout;
    float qs = 1.0f;
    if (MODE == 1) qs = __fdiv_rn(__uint_as_float(g_max[2]), 127.0f);

    float acc[4][4] = {};
    float accT[4][4] = {};
    for (int k0 = 0; k0 < K; k0 += 16) {
        #pragma unroll
        for (int ii = 0; ii < 4; ii++) {
            float a = A[(long long)(m0 + lr + ii) * K + k0 + lc];
            if (MODE == 1) {
                float q = rintf(__fdiv_rn(a, qs));
                a = __fmul_rn(fminf(fmaxf(q, -128.f), 127.f), qs);
            }
            As[lc][lr + ii] = a;
            Ws[lc][lr + ii] = W[(long long)(n0 + lr + ii) * K + k0 + lc];
        }
        __syncthreads();
        #pragma unroll
        for (int kk = 0; kk < 16; kk++) {
            float4 af = *(const float4*)&As[kk][ty * 4];
            float4 wf = *(const float4*)&Ws[kk][tx * 4];
            float aa[4] = {af.x, af.y, af.z, af.w};
            float ww[4] = {wf.x, wf.y, wf.z, wf.w};
            #pragma unroll
            for (int i = 0; i < 4; i++)
                #pragma unroll
                for (int j = 0; j < 4; j++)
                    acc[i][j] = __fmaf_rn(aa[i], ww[j], acc[i][j]);
        }
        if (((k0 + 16) % KC == 0) || (k0 + 16 == K)) {
            #pragma unroll
            for (int i = 0; i < 4; i++)
                #pragma unroll
                for (int j = 0; j < 4; j++) {
                    accT[i][j] = __fadd_rn(accT[i][j], acc[i][j]);
                    acc[i][j] = 0.f;
                }
        }
        __syncthreads();
    }
    #pragma unroll
    for (int i = 0; i < 4; i++)
        #pragma unroll
        for (int j = 0; j < 4; j++)
            C[(long long)(m0 + ty * 4 + i) * N + n0 + tx * 4 + j] =
                __fadd_rn(accT[i][j], bias[n0 + tx * 4 + j]);
}

// ---- score tile: bitwise-identical to R14 ----------------------------------
__device__ __forceinline__ void score_tile(const float* __restrict__ Qs,
                                           const float* __restrict__ Ks,
                                           int ty, int tx, int qt, int kb,
                                           float s[4][4]) {
    float a0[4][4] = {};
    #pragma unroll 8
    for (int d = 0; d < 64; d++) {
        float4 qf = *(const float4*)&Qs[d * 64 + ty * 4];
        float4 kf = *(const float4*)&Ks[d * 64 + tx * 4];
        float qa[4] = {qf.x, qf.y, qf.z, qf.w};
        float ka[4] = {kf.x, kf.y, kf.z, kf.w};
        #pragma unroll
        for (int i = 0; i < 4; i++)
            #pragma unroll
            for (int j = 0; j < 4; j++)
                a0[i][j] = __fmaf_rn(qa[i], ka[j], a0[i][j]);
    }
    #pragma unroll
    for (int i = 0; i < 4; i++)
        #pragma unroll
        for (int j = 0; j < 4; j++) {
            float v = __fmul_rn(a0[i][j], 0.125f);
            if (kb == qt && (tx * 4 + j) > (ty * 4 + i)) v = __fadd_rn(v, NEGM);
            s[i][j] = v;
        }
}

// ---- stage 1: scores once -> S; per-(row,tile) max -> pmax -----------------
__global__ void k_score() {
    __shared__ float Qs[4096];
    __shared__ float Ks[4096];
    const int tid = threadIdx.x;
    const int ty = tid >> 4, tx = tid & 15;
    const int qt = blockIdx.x;
    const int bh = blockIdx.y;
    const int b = bh >> 4, h = bh & 15;
    const int q0 = qt * 64;

    const float* qbase = g_qkv + ((long long)(b * SS + q0)) * D3 + h * HD;
    for (int idx = tid; idx < 4096; idx += 256) {
        int r = idx >> 6, d = idx & 63;
        Qs[d * 64 + r] = qbase[(long long)r * D3 + d];
    }
    const float* kbase = g_qkv + (long long)b * SS * D3 + DD + h * HD;
    float* Srow = g_S + (long long)bh * SS * SS;

    for (int kb = 0; kb <= qt; kb++) {
        __syncthreads();
        const int c0 = kb * 64;
        for (int idx = tid; idx < 4096; idx += 256) {
            int c = idx >> 6, d = idx & 63;
            Ks[d * 64 + c] = kbase[(long long)(c0 + c) * D3 + d];
        }
        __syncthreads();
        float s[4][4];
        score_tile(Qs, Ks, ty, tx, qt, kb, s);
        #pragma unroll
        for (int i = 0; i < 4; i++) {
            float4 v = make_float4(s[i][0], s[i][1], s[i][2], s[i][3]);
            *(float4*)&Srow[(long long)(q0 + ty * 4 + i) * SS + c0 + tx * 4] = v;
            // per-(row, tile) max (order-independent)
            float rm = fmaxf(fmaxf(s[i][0], s[i][1]), fmaxf(s[i][2], s[i][3]));
            #pragma unroll
            for (int ofs = 1; ofs < 16; ofs <<= 1)
                rm = fmaxf(rm, __shfl_xor_sync(0xffffffffu, rm, ofs));
            if (tx == 0)
                g_pmax[((long long)bh * SS + q0 + ty * 4 + i) * 32 + kb] = rm;
        }
    }
}

// ---- stage 2: softmax (R14 order) + PV panels, reading cached S ------------
__global__ void k_attn2() {
    __shared__ float Vs[4096];
    __shared__ float Ps[4096];
    __shared__ float Lrow[64];
    const int tid = threadIdx.x;
    const int ty = tid >> 4, tx = tid & 15;
    const int qt = blockIdx.x;
    const int bh = blockIdx.y;
    const int b = bh >> 4, h = bh & 15;
    const int q0 = qt * 64;

    float* Srow = g_S + (long long)bh * SS * SS;
    const float* vbase = g_qkv + (long long)b * SS * D3 + 2 * DD + h * HD;

    // mrow from pmax (fmaxf over tiles, order-independent)
    float mrow[4];
    #pragma unroll
    for (int i = 0; i < 4; i++) {
        const float* pm = g_pmax + ((long long)bh * SS + q0 + ty * 4 + i) * 32;
        float m = -INFINITY;
        for (int kb = 0; kb <= qt; kb++) m = fmaxf(m, pm[kb]);
        mrow[i] = m;
    }

    // pass A: e = exp(s - m) in place; l accumulated in R14's exact order
    float lrow[4] = {0.f, 0.f, 0.f, 0.f};
    for (int kb = 0; kb <= qt; kb++) {
        const int c0 = kb * 64;
        #pragma unroll
        for (int i = 0; i < 4; i++) {
            float* p = &Srow[(long long)(q0 + ty * 4 + i) * SS + c0 + tx * 4];
            float4 v = *(float4*)p;
            float e0 = xla_expf(__fadd_rn(v.x, -mrow[i]));
            float e1 = xla_expf(__fadd_rn(v.y, -mrow[i]));
            float e2 = xla_expf(__fadd_rn(v.z, -mrow[i]));
            float e3 = xla_expf(__fadd_rn(v.w, -mrow[i]));
            *(float4*)p = make_float4(e0, e1, e2, e3);
            float rs = __fadd_rn(__fadd_rn(__fadd_rn(e0, e1), e2), e3);
            #pragma unroll
            for (int ofs = 1; ofs < 16; ofs <<= 1)
                rs = __fadd_rn(rs, __shfl_xor_sync(0xffffffffu, rs, ofs));
            lrow[i] = __fadd_rn(lrow[i], rs);
        }
    }
    if (tx == 0) {
        #pragma unroll
        for (int i = 0; i < 4; i++) Lrow[ty * 4 + i] = lrow[i];
    }
    __syncthreads();

    // pass B: p = e/l per element; O via 512-key panels, serial chains
    float o[4][4] = {};
    float op[4][4] = {};
    for (int kb = 0; kb <= qt; kb++) {
        __syncthreads();
        const int c0 = kb * 64;
        for (int idx = tid; idx < 4096; idx += 256) {
            int r = idx >> 6, c = idx & 63;
            Ps[c * 64 + r] =
                __fdiv_rn(Srow[(long long)(q0 + r) * SS + c0 + c], Lrow[r]);
            Vs[r * 64 + c] = vbase[(long long)(c0 + r) * D3 + c];
        }
        __syncthreads();
        #pragma unroll 8
        for (int c = 0; c < 64; c++) {
            float4 pf = *(const float4*)&Ps[c * 64 + ty * 4];
            float4 vf = *(const float4*)&Vs[c * 64 + tx * 4];
            float pa[4] = {pf.x, pf.y, pf.z, pf.w};
            float va[4] = {vf.x, vf.y, vf.z, vf.w};
            #pragma unroll
            for (int i = 0; i < 4; i++)
                #pragma unroll
                for (int j = 0; j < 4; j++)
                    op[i][j] = __fmaf_rn(pa[i], va[j], op[i][j]);
        }
        if (((kb + 1) % KCPV_TILES == 0) || (kb == qt)) {
            #pragma unroll
            for (int i = 0; i < 4; i++)
                #pragma unroll
                for (int j = 0; j < 4; j++) {
                    o[i][j] = __fadd_rn(o[i][j], op[i][j]);
                    op[i][j] = 0.f;
                }
        }
    }

    float* obase = g_attn + ((long long)(b * SS + q0)) * DD + h * HD;
    #pragma unroll
    for (int i = 0; i < 4; i++)
        #pragma unroll
        for (int j = 0; j < 4; j++)
            obase[(long long)(ty * 4 + i) * DD + tx * 4 + j] = o[i][j];
}

// ---- launch -----------------------------------------------------------------
extern "C" void kernel_launch(void* const* d_in, const int* in_sizes, int n_in,
                              void* d_out, int out_size) {
    const float* hidden = (const float*)d_in[0];
    const float* W_attn = (const float*)d_in[2];
    const float* b_attn = (const float*)d_in[3];
    const float* W_proj = (const float*)d_in[4];
    const float* b_proj = (const float*)d_in[5];
    float* out = (float*)d_out;

    const long long total = (long long)BB * SS * DD;
    float* present = (out_size >= (int)(3 * total)) ? (out + total) : nullptr;

    k_gemm<0><<<dim3(D3 / 64, (BB * SS) / 64), 256>>>(hidden, W_attn, b_attn, nullptr,
                                                      BB * SS, D3, DD);
    k_init<<<1, 32>>>();
    k_absmax_kv<<<1024, 256>>>();
    k_quant_kv<<<2048, 256>>>(present);
    k_score<<<dim3(SS / 64, BB * HH), 256>>>();
    k_attn2<<<dim3(SS / 64, BB * HH), 256>>>();
    k_absmax_o<<<1024, 256>>>();
    k_gemm<1><<<dim3(DD / 64, (BB * SS) / 64), 256>>>(nullptr, W_proj, b_proj, out,
                                                      BB * SS, DD, DD);
}

// round 17
// speedup vs baseline: 2.4962x; 1.3718x over previous
#include <cuda_runtime.h>
#include <math.h>

#define BB 2
#define SS 2048
#define DD 1024
#define HH 16
#define HD 64
#define D3 3072
#define NEGM (-1e9f)
#define KC 512          // reference panel depth (R14 WIN, frozen)
#define KCPV_TILES 8    // PV panel = 8 tiles * 64 = 512 keys

__device__ float g_qkv[(size_t)BB * SS * D3];
__device__ float g_attn[(size_t)BB * SS * DD];
__device__ float g_S[(size_t)BB * HH * SS * SS];     // scores -> e scratch
__device__ float g_pmax[(size_t)BB * HH * SS * 32];  // per-(row,tile) max
__device__ unsigned g_max[3];

// ---- XLA GenerateVF32Exp (frozen) ------------------------------------------
__device__ __forceinline__ float xla_expf(float x) {
    x = fminf(fmaxf(x, -88.3762626647949f), 88.3762626647950f);
    float fx = floorf(__fmaf_rn(x, 1.44269504088896341f, 0.5f));
    float tmp = __fmul_rn(fx, 0.693359375f);
    float z = __fmul_rn(fx, -2.12194440e-4f);
    x = __fadd_rn(x, -tmp);
    x = __fadd_rn(x, -z);
    z = __fmul_rn(x, x);
    float y = 1.9875691500e-4f;
    y = __fmaf_rn(y, x, 1.3981999507e-3f);
    y = __fmaf_rn(y, x, 8.3334519073e-3f);
    y = __fmaf_rn(y, x, 4.1665795894e-2f);
    y = __fmaf_rn(y, x, 1.6666665459e-1f);
    y = __fmaf_rn(y, x, 5.0000001201e-1f);
    y = __fmaf_rn(y, z, x);
    y = __fadd_rn(y, 1.0f);
    int n = (int)fx;
    float p2n = __int_as_float((n + 127) << 23);
    return __fmul_rn(y, p2n);
}

__device__ __forceinline__ float qz(float a, float qs) {
    float q = rintf(__fdiv_rn(a, qs));
    return __fmul_rn(fminf(fmaxf(q, -128.f), 127.f), qs);
}

__global__ void k_init() {
    if (threadIdx.x < 3) g_max[threadIdx.x] = 0u;
}

__global__ void k_absmax_kv() {
    const long long n = (long long)BB * SS * DD;
    float mk = 0.f, mv = 0.f;
    for (long long i = (long long)blockIdx.x * blockDim.x + threadIdx.x; i < n;
         i += (long long)gridDim.x * blockDim.x) {
        long long bs = i >> 10;
        int c = (int)(i & 1023);
        const float* row = g_qkv + bs * D3;
        mk = fmaxf(mk, fabsf(row[DD + c]));
        mv = fmaxf(mv, fabsf(row[2 * DD + c]));
    }
    #pragma unroll
    for (int o = 16; o; o >>= 1) {
        mk = fmaxf(mk, __shfl_xor_sync(0xffffffffu, mk, o));
        mv = fmaxf(mv, __shfl_xor_sync(0xffffffffu, mv, o));
    }
    if ((threadIdx.x & 31) == 0) {
        atomicMax(&g_max[0], __float_as_uint(mk));
        atomicMax(&g_max[1], __float_as_uint(mv));
    }
}

__global__ void k_absmax_o() {
    const long long n = (long long)BB * SS * DD;
    float m = 0.f;
    for (long long i = (long long)blockIdx.x * blockDim.x + threadIdx.x; i < n;
         i += (long long)gridDim.x * blockDim.x)
        m = fmaxf(m, fabsf(g_attn[i]));
    #pragma unroll
    for (int o = 16; o; o >>= 1) m = fmaxf(m, __shfl_xor_sync(0xffffffffu, m, o));
    if ((threadIdx.x & 31) == 0) atomicMax(&g_max[2], __float_as_uint(m));
}

__global__ void k_quant_kv(float* __restrict__ present) {
    const long long total = (long long)BB * SS * DD;
    const float sk = __fdiv_rn(__uint_as_float(g_max[0]), 127.0f);
    const float sv = __fdiv_rn(__uint_as_float(g_max[1]), 127.0f);
    for (long long t = (long long)blockIdx.x * blockDim.x + threadIdx.x; t < 2 * total;
         t += (long long)gridDim.x * blockDim.x) {
        int half = (int)(t / total);
        long long i = t - (long long)half * total;
        long long bs = i >> 10;
        int c = (int)(i & 1023);
        float sc = half ? sv : sk;
        long long adr = bs * D3 + (long long)DD * (1 + half) + c;
        float q = qz(g_qkv[adr], sc);
        g_qkv[adr] = q;
        if (present) {
            int h = c >> 6, d = c & 63;
            int s = (int)(bs & (SS - 1));
            int b = (int)(bs >> 11);
            present[(long long)half * total +
                    (((long long)(b * HH + h) * SS + s) << 6) + d] = q;
        }
    }
}

// ---- SGEMM: 128x128 block, 8x8 microtile; serial ascending-k chains inside
// kc=512 panels; panel partials merged through C (same fadd sequence as accT).
template <int MODE>
__global__ void __launch_bounds__(256) k_gemm(
        const float* __restrict__ Ain, const float* __restrict__ W,
        const float* __restrict__ bias, float* __restrict__ Cout,
        int M, int N, int K) {
    __shared__ float As[16][132];
    __shared__ float Ws[16][132];
    const int tid = threadIdx.x;
    const int ty = tid >> 4, tx = tid & 15;
    const int m0 = blockIdx.y * 128, n0 = blockIdx.x * 128;
    const int lrow = tid >> 2;          // 0..63
    const int lk = (tid & 3) * 4;       // 0,4,8,12

    const float* A = (MODE == 0) ? Ain : g_attn;
    float* C = (MODE == 0) ? g_qkv : Cout;
    float qs = 1.0f;
    if (MODE == 1) qs = __fdiv_rn(__uint_as_float(g_max[2]), 127.0f);

    const int nPanels = (K + KC - 1) / KC;
    for (int panel = 0; panel < nPanels; panel++) {
        const int kbeg = panel * KC;
        const int kend = (kbeg + KC < K) ? kbeg + KC : K;
        float acc[8][8] = {};
        for (int k0 = kbeg; k0 < kend; k0 += 16) {
            #pragma unroll
            for (int half = 0; half < 2; half++) {
                int row = lrow + half * 64;
                float4 av = *(const float4*)&A[(long long)(m0 + row) * K + k0 + lk];
                if (MODE == 1) {
                    av.x = qz(av.x, qs);
                    av.y = qz(av.y, qs);
                    av.z = qz(av.z, qs);
                    av.w = qz(av.w, qs);
                }
                As[lk + 0][row] = av.x;
                As[lk + 1][row] = av.y;
                As[lk + 2][row] = av.z;
                As[lk + 3][row] = av.w;
                float4 wv = *(const float4*)&W[(long long)(n0 + row) * K + k0 + lk];
                Ws[lk + 0][row] = wv.x;
                Ws[lk + 1][row] = wv.y;
                Ws[lk + 2][row] = wv.z;
                Ws[lk + 3][row] = wv.w;
            }
            __syncthreads();
            #pragma unroll
            for (int kk = 0; kk < 16; kk++) {   // ascending k, serial/element
                float a[8], w[8];
                *(float4*)&a[0] = *(const float4*)&As[kk][ty * 8];
                *(float4*)&a[4] = *(const float4*)&As[kk][ty * 8 + 4];
                *(float4*)&w[0] = *(const float4*)&Ws[kk][tx * 8];
                *(float4*)&w[4] = *(const float4*)&Ws[kk][tx * 8 + 4];
                #pragma unroll
                for (int i = 0; i < 8; i++)
                    #pragma unroll
                    for (int j = 0; j < 8; j++)
                        acc[i][j] = __fmaf_rn(a[i], w[j], acc[i][j]);
            }
            __syncthreads();
        }
        const bool last = (panel == nPanels - 1);
        #pragma unroll
        for (int i = 0; i < 8; i++)
            #pragma unroll
            for (int j = 0; j < 8; j++) {
                long long cidx =
                    (long long)(m0 + ty * 8 + i) * N + n0 + tx * 8 + j;
                float v = acc[i][j];
                if (panel > 0) v = __fadd_rn(C[cidx], v);
                if (last) v = __fadd_rn(v, bias[n0 + tx * 8 + j]);
                C[cidx] = v;
            }
    }
}

// ---- score tile (frozen bitwise) -------------------------------------------
__device__ __forceinline__ void score_tile(const float* __restrict__ Qs,
                                           const float* __restrict__ Ks,
                                           int ty, int tx, int qt, int kb,
                                           float s[4][4]) {
    float a0[4][4] = {};
    #pragma unroll 8
    for (int d = 0; d < 64; d++) {
        float4 qf = *(const float4*)&Qs[d * 64 + ty * 4];
        float4 kf = *(const float4*)&Ks[d * 64 + tx * 4];
        float qa[4] = {qf.x, qf.y, qf.z, qf.w};
        float ka[4] = {kf.x, kf.y, kf.z, kf.w};
        #pragma unroll
        for (int i = 0; i < 4; i++)
            #pragma unroll
            for (int j = 0; j < 4; j++)
                a0[i][j] = __fmaf_rn(qa[i], ka[j], a0[i][j]);
    }
    #pragma unroll
    for (int i = 0; i < 4; i++)
        #pragma unroll
        for (int j = 0; j < 4; j++) {
            float v = __fmul_rn(a0[i][j], 0.125f);
            if (kb == qt && (tx * 4 + j) > (ty * 4 + i)) v = __fadd_rn(v, NEGM);
            s[i][j] = v;
        }
}

// ---- stage 1: scores once -> S; per-(row,tile) max -> pmax -----------------
__global__ void k_score() {
    __shared__ float Qs[4096];
    __shared__ float Ks[4096];
    const int tid = threadIdx.x;
    const int ty = tid >> 4, tx = tid & 15;
    const int qt = blockIdx.x;
    const int bh = blockIdx.y;
    const int b = bh >> 4, h = bh & 15;
    const int q0 = qt * 64;

    const float* qbase = g_qkv + ((long long)(b * SS + q0)) * D3 + h * HD;
    for (int idx = tid; idx < 4096; idx += 256) {
        int r = idx >> 6, d = idx & 63;
        Qs[d * 64 + r] = qbase[(long long)r * D3 + d];
    }
    const float* kbase = g_qkv + (long long)b * SS * D3 + DD + h * HD;
    float* Srow = g_S + (long long)bh * SS * SS;

    for (int kb = 0; kb <= qt; kb++) {
        __syncthreads();
        const int c0 = kb * 64;
        for (int idx = tid; idx < 4096; idx += 256) {
            int c = idx >> 6, d = idx & 63;
            Ks[d * 64 + c] = kbase[(long long)(c0 + c) * D3 + d];
        }
        __syncthreads();
        float s[4][4];
        score_tile(Qs, Ks, ty, tx, qt, kb, s);
        #pragma unroll
        for (int i = 0; i < 4; i++) {
            float4 v = make_float4(s[i][0], s[i][1], s[i][2], s[i][3]);
            *(float4*)&Srow[(long long)(q0 + ty * 4 + i) * SS + c0 + tx * 4] = v;
            float rm = fmaxf(fmaxf(s[i][0], s[i][1]), fmaxf(s[i][2], s[i][3]));
            #pragma unroll
            for (int ofs = 1; ofs < 16; ofs <<= 1)
                rm = fmaxf(rm, __shfl_xor_sync(0xffffffffu, rm, ofs));
            if (tx == 0)
                g_pmax[((long long)bh * SS + q0 + ty * 4 + i) * 32 + kb] = rm;
        }
    }
}

// ---- stage 2: softmax + PV panels (frozen R16 structure) -------------------
__global__ void k_attn2() {
    __shared__ float Vs[4096];
    __shared__ float Ps[4096];
    __shared__ float Lrow[64];
    const int tid = threadIdx.x;
    const int ty = tid >> 4, tx = tid & 15;
    const int qt = blockIdx.x;
    const int bh = blockIdx.y;
    const int b = bh >> 4, h = bh & 15;
    const int q0 = qt * 64;

    float* Srow = g_S + (long long)bh * SS * SS;
    const float* vbase = g_qkv + (long long)b * SS * D3 + 2 * DD + h * HD;

    float mrow[4];
    #pragma unroll
    for (int i = 0; i < 4; i++) {
        const float* pm = g_pmax + ((long long)bh * SS + q0 + ty * 4 + i) * 32;
        float m = -INFINITY;
        for (int kb = 0; kb <= qt; kb++) m = fmaxf(m, pm[kb]);
        mrow[i] = m;
    }

    float lrow[4] = {0.f, 0.f, 0.f, 0.f};
    for (int kb = 0; kb <= qt; kb++) {
        const int c0 = kb * 64;
        #pragma unroll
        for (int i = 0; i < 4; i++) {
            float* p = &Srow[(long long)(q0 + ty * 4 + i) * SS + c0 + tx * 4];
            float4 v = *(float4*)p;
            float e0 = xla_expf(__fadd_rn(v.x, -mrow[i]));
            float e1 = xla_expf(__fadd_rn(v.y, -mrow[i]));
            float e2 = xla_expf(__fadd_rn(v.z, -mrow[i]));
            float e3 = xla_expf(__fadd_rn(v.w, -mrow[i]));
            *(float4*)p = make_float4(e0, e1, e2, e3);
            float rs = __fadd_rn(__fadd_rn(__fadd_rn(e0, e1), e2), e3);
            #pragma unroll
            for (int ofs = 1; ofs < 16; ofs <<= 1)
                rs = __fadd_rn(rs, __shfl_xor_sync(0xffffffffu, rs, ofs));
            lrow[i] = __fadd_rn(lrow[i], rs);
        }
    }
    if (tx == 0) {
        #pragma unroll
        for (int i = 0; i < 4; i++) Lrow[ty * 4 + i] = lrow[i];
    }
    __syncthreads();

    float o[4][4] = {};
    float op[4][4] = {};
    for (int kb = 0; kb <= qt; kb++) {
        __syncthreads();
        const int c0 = kb * 64;
        for (int idx = tid; idx < 4096; idx += 256) {
            int r = idx >> 6, c = idx & 63;
            Ps[c * 64 + r] =
                __fdiv_rn(Srow[(long long)(q0 + r) * SS + c0 + c], Lrow[r]);
            Vs[r * 64 + c] = vbase[(long long)(c0 + r) * D3 + c];
        }
        __syncthreads();
        #pragma unroll 8
        for (int c = 0; c < 64; c++) {
            float4 pf = *(const float4*)&Ps[c * 64 + ty * 4];
            float4 vf = *(const float4*)&Vs[c * 64 + tx * 4];
            float pa[4] = {pf.x, pf.y, pf.z, pf.w};
            float va[4] = {vf.x, vf.y, vf.z, vf.w};
            #pragma unroll
            for (int i = 0; i < 4; i++)
                #pragma unroll
                for (int j = 0; j < 4; j++)
                    op[i][j] = __fmaf_rn(pa[i], va[j], op[i][j]);
        }
        if (((kb + 1) % KCPV_TILES == 0) || (kb == qt)) {
            #pragma unroll
            for (int i = 0; i < 4; i++)
                #pragma unroll
                for (int j = 0; j < 4; j++) {
                    o[i][j] = __fadd_rn(o[i][j], op[i][j]);
                    op[i][j] = 0.f;
                }
        }
    }

    float* obase = g_attn + ((long long)(b * SS + q0)) * DD + h * HD;
    #pragma unroll
    for (int i = 0; i < 4; i++)
        #pragma unroll
        for (int j = 0; j < 4; j++)
            obase[(long long)(ty * 4 + i) * DD + tx * 4 + j] = o[i][j];
}

// ---- launch -----------------------------------------------------------------
extern "C" void kernel_launch(void* const* d_in, const int* in_sizes, int n_in,
                              void* d_out, int out_size) {
    const float* hidden = (const float*)d_in[0];
    const float* W_attn = (const float*)d_in[2];
    const float* b_attn = (const float*)d_in[3];
    const float* W_proj = (const float*)d_in[4];
    const float* b_proj = (const float*)d_in[5];
    float* out = (float*)d_out;

    const long long total = (long long)BB * SS * DD;
    float* present = (out_size >= (int)(3 * total)) ? (out + total) : nullptr;

    k_gemm<0><<<dim3(D3 / 128, (BB * SS) / 128), 256>>>(hidden, W_attn, b_attn,
                                                        nullptr, BB * SS, D3, DD);
    k_init<<<1, 32>>>();
    k_absmax_kv<<<1024, 256>>>();
    k_quant_kv<<<2048, 256>>>(present);
    k_score<<<dim3(SS / 64, BB * HH), 256>>>();
    k_attn2<<<dim3(SS / 64, BB * HH), 256>>>();
    k_absmax_o<<<1024, 256>>>();
    k_gemm<1><<<dim3(DD / 128, (BB * SS) / 128), 256>>>(nullptr, W_proj, b_proj,
                                                        out, BB * SS, DD, DD);
}